// round 3
// baseline (speedup 1.0000x reference)
#include <cuda_runtime.h>
#include <math.h>

#define HID 512
#define SEQ 4096
#define NB  4
#define ATT_SCALE 0.044194173824159216f   // 512^-0.5

// 33.5 MB scratch for q = x @ Wq^T  (static __device__ array: allocation-free)
__device__ float g_q[(size_t)NB * SEQ * HID];

// ---------------------------------------------------------------------------
// Projection GEMM: q[m,e] = sum_d x[m,d] * Wq[e,d]   (M=16384, N=512, K=512)
// Both operands are K-contiguous row-major. 64x64 tile, BK=32, 256 threads,
// 4x4 micro-tile per thread, transposed smem tiles so inner loads are float4.
// ---------------------------------------------------------------------------
__global__ __launch_bounds__(256, 1) void proj_kernel(const float* __restrict__ X,
                                                      const float* __restrict__ W) {
    __shared__ float As[32][68];   // As[k][m]
    __shared__ float Bs[32][68];   // Bs[k][n]
    const int m0 = blockIdx.x * 64;
    const int n0 = blockIdx.y * 64;
    const int tid = threadIdx.x;
    const int ty = tid >> 4;       // 0..15
    const int tx = tid & 15;       // 0..15

    float acc[4][4];
#pragma unroll
    for (int i = 0; i < 4; i++)
#pragma unroll
        for (int j = 0; j < 4; j++) acc[i][j] = 0.f;

    for (int k0 = 0; k0 < HID; k0 += 32) {
#pragma unroll
        for (int l = 0; l < 2; l++) {
            int idx = tid + l * 256;          // 0..511 float4 slots
            int r   = idx >> 3;               // 0..63 tile row
            int c4  = (idx & 7) << 2;         // 0..28 k offset
            float4 va = *(const float4*)(X + (size_t)(m0 + r) * HID + k0 + c4);
            As[c4 + 0][r] = va.x; As[c4 + 1][r] = va.y;
            As[c4 + 2][r] = va.z; As[c4 + 3][r] = va.w;
            float4 vb = *(const float4*)(W + (size_t)(n0 + r) * HID + k0 + c4);
            Bs[c4 + 0][r] = vb.x; Bs[c4 + 1][r] = vb.y;
            Bs[c4 + 2][r] = vb.z; Bs[c4 + 3][r] = vb.w;
        }
        __syncthreads();
#pragma unroll
        for (int kk = 0; kk < 32; kk++) {
            float4 a4 = *(float4*)&As[kk][ty << 2];
            float4 b4 = *(float4*)&Bs[kk][tx << 2];
            float av[4] = {a4.x, a4.y, a4.z, a4.w};
            float bv[4] = {b4.x, b4.y, b4.z, b4.w};
#pragma unroll
            for (int i = 0; i < 4; i++)
#pragma unroll
                for (int j = 0; j < 4; j++)
                    acc[i][j] = fmaf(av[i], bv[j], acc[i][j]);
        }
        __syncthreads();
    }
#pragma unroll
    for (int i = 0; i < 4; i++) {
        float4 v = make_float4(acc[i][0], acc[i][1], acc[i][2], acc[i][3]);
        *(float4*)(g_q + (size_t)(m0 + (ty << 2) + i) * HID + n0 + (tx << 2)) = v;
    }
}

// ---------------------------------------------------------------------------
// Flash attention, fp32. K = V = q, so each 64x512 key tile is loaded once
// and reused for S (Q @ K^T) and PV (P @ V).
//   BM=32 queries per CTA, BN=64 keys per iteration, 256 threads.
//   Smem: Qs[32][516] (resident) + KVs[64][516] + Ps^T[64][36]  ~= 207 KB.
//   Warp w owns query rows 4w..4w+3 (softmax reductions are warp shuffles).
// ---------------------------------------------------------------------------
#define QSTR  516
#define KVSTR 516
#define PSTR  36
#define SMEM_FLOATS (32 * QSTR + 64 * KVSTR + 64 * PSTR)   // 51840 -> 207360 B

__global__ __launch_bounds__(256, 1) void attn_kernel(float* __restrict__ out) {
    extern __shared__ float sm[];
    float* Qs  = sm;                              // [32][QSTR]
    float* KVs = sm + 32 * QSTR;                  // [64][KVSTR]
    float* Ps  = sm + 32 * QSTR + 64 * KVSTR;     // [64][PSTR]  (Ps[key][row])

    const int b  = blockIdx.y;
    const int m0 = blockIdx.x * 32;
    const float* __restrict__ qb = g_q + (size_t)b * SEQ * HID;
    const int tid = threadIdx.x;
    const int tr  = tid >> 5;     // warp id 0..7 -> rows 4tr..4tr+3
    const int tc  = tid & 31;     // lane

    // Load resident Q tile: 32x512 = 4096 float4, 16 per thread
#pragma unroll
    for (int l = 0; l < 16; l++) {
        int idx = tid + l * 256;
        int r   = idx >> 7;
        int c4  = (idx & 127) << 2;
        *(float4*)&Qs[r * QSTR + c4] =
            *(const float4*)(qb + (size_t)(m0 + r) * HID + c4);
    }

    float O[4][16];               // rows i, cols 4*tc + 128*jj + q
#pragma unroll
    for (int i = 0; i < 4; i++)
#pragma unroll
        for (int j = 0; j < 16; j++) O[i][j] = 0.f;
    float mrow[4] = {-INFINITY, -INFINITY, -INFINITY, -INFINITY};
    float lrow[4] = {0.f, 0.f, 0.f, 0.f};

    __syncthreads();

    for (int kt = 0; kt < SEQ; kt += 64) {
        // Load KV tile: 64x512 = 8192 float4, 32 per thread
#pragma unroll
        for (int l = 0; l < 32; l++) {
            int idx = tid + l * 256;
            int r   = idx >> 7;
            int c4  = (idx & 127) << 2;
            *(float4*)&KVs[r * KVSTR + c4] =
                *(const float4*)(qb + (size_t)(kt + r) * HID + c4);
        }
        __syncthreads();

        // ---- S = Q @ K^T : thread covers rows 4tr+i, cols tc and tc+32 ----
        float s[4][2];
#pragma unroll
        for (int i = 0; i < 4; i++) { s[i][0] = 0.f; s[i][1] = 0.f; }
#pragma unroll 4
        for (int k = 0; k < HID; k += 4) {
            float4 b0 = *(float4*)&KVs[tc * KVSTR + k];
            float4 b1 = *(float4*)&KVs[(tc + 32) * KVSTR + k];
#pragma unroll
            for (int i = 0; i < 4; i++) {
                float4 a = *(float4*)&Qs[((tr << 2) + i) * QSTR + k];
                s[i][0] = fmaf(a.x, b0.x, s[i][0]);
                s[i][0] = fmaf(a.y, b0.y, s[i][0]);
                s[i][0] = fmaf(a.z, b0.z, s[i][0]);
                s[i][0] = fmaf(a.w, b0.w, s[i][0]);
                s[i][1] = fmaf(a.x, b1.x, s[i][1]);
                s[i][1] = fmaf(a.y, b1.y, s[i][1]);
                s[i][1] = fmaf(a.z, b1.z, s[i][1]);
                s[i][1] = fmaf(a.w, b1.w, s[i][1]);
            }
        }

        // ---- online softmax (each warp fully owns its 4 rows) ----
        float alpha[4];
#pragma unroll
        for (int i = 0; i < 4; i++) {
            float s0 = s[i][0] * ATT_SCALE;
            float s1 = s[i][1] * ATT_SCALE;
            float v = fmaxf(s0, s1);
#pragma unroll
            for (int off = 16; off > 0; off >>= 1)
                v = fmaxf(v, __shfl_xor_sync(0xffffffffu, v, off));
            float mnew = fmaxf(mrow[i], v);
            alpha[i] = __expf(mrow[i] - mnew);
            float p0 = __expf(s0 - mnew);
            float p1 = __expf(s1 - mnew);
            mrow[i] = mnew;
            s[i][0] = p0;
            s[i][1] = p1;
            float rs = p0 + p1;
#pragma unroll
            for (int off = 16; off > 0; off >>= 1)
                rs += __shfl_xor_sync(0xffffffffu, rs, off);
            lrow[i] = lrow[i] * alpha[i] + rs;
        }
#pragma unroll
        for (int i = 0; i < 4; i++)
#pragma unroll
            for (int j = 0; j < 16; j++) O[i][j] *= alpha[i];

        // Store P transposed: Ps[key][row], float4 over the 4 owned rows
        *(float4*)&Ps[tc * PSTR + (tr << 2)] =
            make_float4(s[0][0], s[1][0], s[2][0], s[3][0]);
        *(float4*)&Ps[(tc + 32) * PSTR + (tr << 2)] =
            make_float4(s[0][1], s[1][1], s[2][1], s[3][1]);
        __syncthreads();

        // ---- O += P @ V : A is warp-broadcast float4, B conflict-free ----
#pragma unroll 2
        for (int k = 0; k < 64; k++) {
            float4 a = *(float4*)&Ps[k * PSTR + (tr << 2)];
            float av[4] = {a.x, a.y, a.z, a.w};
#pragma unroll
            for (int jj = 0; jj < 4; jj++) {
                float4 bv = *(float4*)&KVs[k * KVSTR + (tc << 2) + (jj << 7)];
#pragma unroll
                for (int i = 0; i < 4; i++) {
                    O[i][jj * 4 + 0] = fmaf(av[i], bv.x, O[i][jj * 4 + 0]);
                    O[i][jj * 4 + 1] = fmaf(av[i], bv.y, O[i][jj * 4 + 1]);
                    O[i][jj * 4 + 2] = fmaf(av[i], bv.z, O[i][jj * 4 + 2]);
                    O[i][jj * 4 + 3] = fmaf(av[i], bv.w, O[i][jj * 4 + 3]);
                }
            }
        }
        __syncthreads();   // KVs/Ps reused next iteration
    }

    // ---- finalize: divide by softmax denominator, write out ----
#pragma unroll
    for (int i = 0; i < 4; i++) {
        float inv = 1.0f / lrow[i];
#pragma unroll
        for (int jj = 0; jj < 4; jj++) {
            float4 v = make_float4(O[i][jj * 4 + 0] * inv,
                                   O[i][jj * 4 + 1] * inv,
                                   O[i][jj * 4 + 2] * inv,
                                   O[i][jj * 4 + 3] * inv);
            *(float4*)(out + (size_t)((b * SEQ) + m0 + (tr << 2) + i) * HID +
                       (tc << 2) + (jj << 7)) = v;
        }
    }
}

extern "C" void kernel_launch(void* const* d_in, const int* in_sizes, int n_in,
                              void* d_out, int out_size) {
    (void)in_sizes; (void)n_in; (void)out_size;
    const float* x = (const float*)d_in[0];
    const float* W = (const float*)d_in[1];
    float* out = (float*)d_out;

    const int smem_bytes = SMEM_FLOATS * (int)sizeof(float);   // 207360
    cudaFuncSetAttribute(attn_kernel,
                         cudaFuncAttributeMaxDynamicSharedMemorySize, smem_bytes);

    dim3 pg(NB * SEQ / 64, HID / 64);     // (256, 8)
    proj_kernel<<<pg, 256>>>(x, W);

    dim3 ag(SEQ / 32, NB);                // (128, 4)
    attn_kernel<<<ag, 256, smem_bytes>>>(out);
}

// round 7
// speedup vs baseline: 1.0002x; 1.0002x over previous
#include <cuda_runtime.h>
#include <math.h>

#define HID 512
#define SEQ 4096
#define NB  4
#define ATT_SCALE 0.044194173824159216f   // 512^-0.5

// 33.5 MB scratch for q = x @ Wq^T  (static __device__ array: allocation-free)
__device__ float g_q[(size_t)NB * SEQ * HID];

// ---------------------------------------------------------------------------
// Projection GEMM: q[m,e] = sum_d x[m,d] * Wq[e,d]   (M=16384, N=512, K=512)
// Both operands are K-contiguous row-major. 64x64 tile, BK=32, 256 threads,
// 4x4 micro-tile per thread, transposed smem tiles so inner loads are float4.
// ---------------------------------------------------------------------------
__global__ __launch_bounds__(256, 1) void proj_kernel(const float* __restrict__ X,
                                                      const float* __restrict__ W) {
    __shared__ float As[32][68];   // As[k][m]
    __shared__ float Bs[32][68];   // Bs[k][n]
    const int m0 = blockIdx.x * 64;
    const int n0 = blockIdx.y * 64;
    const int tid = threadIdx.x;
    const int ty = tid >> 4;       // 0..15
    const int tx = tid & 15;       // 0..15

    float acc[4][4];
#pragma unroll
    for (int i = 0; i < 4; i++)
#pragma unroll
        for (int j = 0; j < 4; j++) acc[i][j] = 0.f;

    for (int k0 = 0; k0 < HID; k0 += 32) {
#pragma unroll
        for (int l = 0; l < 2; l++) {
            int idx = tid + l * 256;          // 0..511 float4 slots
            int r   = idx >> 3;               // 0..63 tile row
            int c4  = (idx & 7) << 2;         // 0..28 k offset
            float4 va = *(const float4*)(X + (size_t)(m0 + r) * HID + k0 + c4);
            As[c4 + 0][r] = va.x; As[c4 + 1][r] = va.y;
            As[c4 + 2][r] = va.z; As[c4 + 3][r] = va.w;
            float4 vb = *(const float4*)(W + (size_t)(n0 + r) * HID + k0 + c4);
            Bs[c4 + 0][r] = vb.x; Bs[c4 + 1][r] = vb.y;
            Bs[c4 + 2][r] = vb.z; Bs[c4 + 3][r] = vb.w;
        }
        __syncthreads();
#pragma unroll
        for (int kk = 0; kk < 32; kk++) {
            float4 a4 = *(float4*)&As[kk][ty << 2];
            float4 b4 = *(float4*)&Bs[kk][tx << 2];
            float av[4] = {a4.x, a4.y, a4.z, a4.w};
            float bv[4] = {b4.x, b4.y, b4.z, b4.w};
#pragma unroll
            for (int i = 0; i < 4; i++)
#pragma unroll
                for (int j = 0; j < 4; j++)
                    acc[i][j] = fmaf(av[i], bv[j], acc[i][j]);
        }
        __syncthreads();
    }
#pragma unroll
    for (int i = 0; i < 4; i++) {
        float4 v = make_float4(acc[i][0], acc[i][1], acc[i][2], acc[i][3]);
        *(float4*)(g_q + (size_t)(m0 + (ty << 2) + i) * HID + n0 + (tx << 2)) = v;
    }
}

// ---------------------------------------------------------------------------
// Flash attention, fp32. K = V = q, so each 64x512 key tile is loaded once
// and reused for S (Q @ K^T) and PV (P @ V).
//   BM=32 queries per CTA, BN=64 keys per iteration, 256 threads.
//   Smem: Qs[32][516] (resident) + KVs[64][516] + Ps^T[64][36]  ~= 207 KB.
//   Warp w owns query rows 4w..4w+3 (softmax reductions are warp shuffles).
// ---------------------------------------------------------------------------
#define QSTR  516
#define KVSTR 516
#define PSTR  36
#define SMEM_FLOATS (32 * QSTR + 64 * KVSTR + 64 * PSTR)   // 51840 -> 207360 B

__global__ __launch_bounds__(256, 1) void attn_kernel(float* __restrict__ out) {
    extern __shared__ float sm[];
    float* Qs  = sm;                              // [32][QSTR]
    float* KVs = sm + 32 * QSTR;                  // [64][KVSTR]
    float* Ps  = sm + 32 * QSTR + 64 * KVSTR;     // [64][PSTR]  (Ps[key][row])

    const int b  = blockIdx.y;
    const int m0 = blockIdx.x * 32;
    const float* __restrict__ qb = g_q + (size_t)b * SEQ * HID;
    const int tid = threadIdx.x;
    const int tr  = tid >> 5;     // warp id 0..7 -> rows 4tr..4tr+3
    const int tc  = tid & 31;     // lane

    // Load resident Q tile: 32x512 = 4096 float4, 16 per thread
#pragma unroll
    for (int l = 0; l < 16; l++) {
        int idx = tid + l * 256;
        int r   = idx >> 7;
        int c4  = (idx & 127) << 2;
        *(float4*)&Qs[r * QSTR + c4] =
            *(const float4*)(qb + (size_t)(m0 + r) * HID + c4);
    }

    float O[4][16];               // rows i, cols 4*tc + 128*jj + q
#pragma unroll
    for (int i = 0; i < 4; i++)
#pragma unroll
        for (int j = 0; j < 16; j++) O[i][j] = 0.f;
    float mrow[4] = {-INFINITY, -INFINITY, -INFINITY, -INFINITY};
    float lrow[4] = {0.f, 0.f, 0.f, 0.f};

    __syncthreads();

    for (int kt = 0; kt < SEQ; kt += 64) {
        // Load KV tile: 64x512 = 8192 float4, 32 per thread
#pragma unroll
        for (int l = 0; l < 32; l++) {
            int idx = tid + l * 256;
            int r   = idx >> 7;
            int c4  = (idx & 127) << 2;
            *(float4*)&KVs[r * KVSTR + c4] =
                *(const float4*)(qb + (size_t)(kt + r) * HID + c4);
        }
        __syncthreads();

        // ---- S = Q @ K^T : thread covers rows 4tr+i, cols tc and tc+32 ----
        float s[4][2];
#pragma unroll
        for (int i = 0; i < 4; i++) { s[i][0] = 0.f; s[i][1] = 0.f; }
#pragma unroll 4
        for (int k = 0; k < HID; k += 4) {
            float4 b0 = *(float4*)&KVs[tc * KVSTR + k];
            float4 b1 = *(float4*)&KVs[(tc + 32) * KVSTR + k];
#pragma unroll
            for (int i = 0; i < 4; i++) {
                float4 a = *(float4*)&Qs[((tr << 2) + i) * QSTR + k];
                s[i][0] = fmaf(a.x, b0.x, s[i][0]);
                s[i][0] = fmaf(a.y, b0.y, s[i][0]);
                s[i][0] = fmaf(a.z, b0.z, s[i][0]);
                s[i][0] = fmaf(a.w, b0.w, s[i][0]);
                s[i][1] = fmaf(a.x, b1.x, s[i][1]);
                s[i][1] = fmaf(a.y, b1.y, s[i][1]);
                s[i][1] = fmaf(a.z, b1.z, s[i][1]);
                s[i][1] = fmaf(a.w, b1.w, s[i][1]);
            }
        }

        // ---- online softmax (each warp fully owns its 4 rows) ----
        float alpha[4];
#pragma unroll
        for (int i = 0; i < 4; i++) {
            float s0 = s[i][0] * ATT_SCALE;
            float s1 = s[i][1] * ATT_SCALE;
            float v = fmaxf(s0, s1);
#pragma unroll
            for (int off = 16; off > 0; off >>= 1)
                v = fmaxf(v, __shfl_xor_sync(0xffffffffu, v, off));
            float mnew = fmaxf(mrow[i], v);
            alpha[i] = __expf(mrow[i] - mnew);
            float p0 = __expf(s0 - mnew);
            float p1 = __expf(s1 - mnew);
            mrow[i] = mnew;
            s[i][0] = p0;
            s[i][1] = p1;
            float rs = p0 + p1;
#pragma unroll
            for (int off = 16; off > 0; off >>= 1)
                rs += __shfl_xor_sync(0xffffffffu, rs, off);
            lrow[i] = lrow[i] * alpha[i] + rs;
        }
#pragma unroll
        for (int i = 0; i < 4; i++)
#pragma unroll
            for (int j = 0; j < 16; j++) O[i][j] *= alpha[i];

        // Store P transposed: Ps[key][row], float4 over the 4 owned rows
        *(float4*)&Ps[tc * PSTR + (tr << 2)] =
            make_float4(s[0][0], s[1][0], s[2][0], s[3][0]);
        *(float4*)&Ps[(tc + 32) * PSTR + (tr << 2)] =
            make_float4(s[0][1], s[1][1], s[2][1], s[3][1]);
        __syncthreads();

        // ---- O += P @ V : A is warp-broadcast float4, B conflict-free ----
#pragma unroll 2
        for (int k = 0; k < 64; k++) {
            float4 a = *(float4*)&Ps[k * PSTR + (tr << 2)];
            float av[4] = {a.x, a.y, a.z, a.w};
#pragma unroll
            for (int jj = 0; jj < 4; jj++) {
                float4 bv = *(float4*)&KVs[k * KVSTR + (tc << 2) + (jj << 7)];
#pragma unroll
                for (int i = 0; i < 4; i++) {
                    O[i][jj * 4 + 0] = fmaf(av[i], bv.x, O[i][jj * 4 + 0]);
                    O[i][jj * 4 + 1] = fmaf(av[i], bv.y, O[i][jj * 4 + 1]);
                    O[i][jj * 4 + 2] = fmaf(av[i], bv.z, O[i][jj * 4 + 2]);
                    O[i][jj * 4 + 3] = fmaf(av[i], bv.w, O[i][jj * 4 + 3]);
                }
            }
        }
        __syncthreads();   // KVs/Ps reused next iteration
    }

    // ---- finalize: divide by softmax denominator, write out ----
#pragma unroll
    for (int i = 0; i < 4; i++) {
        float inv = 1.0f / lrow[i];
#pragma unroll
        for (int jj = 0; jj < 4; jj++) {
            float4 v = make_float4(O[i][jj * 4 + 0] * inv,
                                   O[i][jj * 4 + 1] * inv,
                                   O[i][jj * 4 + 2] * inv,
                                   O[i][jj * 4 + 3] * inv);
            *(float4*)(out + (size_t)((b * SEQ) + m0 + (tr << 2) + i) * HID +
                       (tc << 2) + (jj << 7)) = v;
        }
    }
}

extern "C" void kernel_launch(void* const* d_in, const int* in_sizes, int n_in,
                              void* d_out, int out_size) {
    (void)in_sizes; (void)n_in; (void)out_size;
    const float* x = (const float*)d_in[0];
    const float* W = (const float*)d_in[1];
    float* out = (float*)d_out;

    const int smem_bytes = SMEM_FLOATS * (int)sizeof(float);   // 207360
    cudaFuncSetAttribute(attn_kernel,
                         cudaFuncAttributeMaxDynamicSharedMemorySize, smem_bytes);

    dim3 pg(NB * SEQ / 64, HID / 64);     // (256, 8)
    proj_kernel<<<pg, 256>>>(x, W);

    dim3 ag(SEQ / 32, NB);                // (128, 4)
    attn_kernel<<<ag, 256, smem_bytes>>>(out);
}